// round 15
// baseline (speedup 1.0000x reference)
#include <cuda_runtime.h>
#include <cstddef>
#include <cstdint>

// DCTFeatureModel — collapsed linear model:
// feat[b,s,o] = sum_{t,ij} xc[b,s,t,ij] * Veff[s,o,t,ij] + bias[s,o]
//   xc[b,s,t,ij]    = sum_c x[b, s*256 + c*32 + t, ij]
//   Veff[s,o,t,i,j] = (1/8) sum_{f,p,q} Ct[f,t] Cs[p,i] Cs[q,j] W[s,o,f,p,q]
// out[b, s*64+o] = leaky_relu(feat)
//
// R15 = R13 with ONE change: the phase-0 x prefetch moved from before the
// slice spin to AFTER it (R4-exact prologue). Rationale: the 33MB phase-0
// x burst was contending with the W->veff->flag critical path that every
// CTA's spin waits on; x gains nothing from being early.

#define NSW 2
#define NF 64
#define KSPLIT 16
#define MTILES 16

__device__ __align__(16) float g_veff[NSW * 32 * 64 * 64];        // [s][t][ij][o], 1 MB
__device__ __align__(16) float g_part[KSPLIT * 1024 * NSW * NF];  // 8 MB
__device__ int g_flag[32];  // per-(s,ks) slice arrival counters; epi resets

typedef unsigned long long u64;

__device__ __forceinline__ u64 pk2(float a, float b) {
    u64 r; asm("mov.b64 %0,{%1,%2};" : "=l"(r) : "f"(a), "f"(b)); return r;
}
__device__ __forceinline__ float2 up2(u64 a) {
    float2 v; asm("mov.b64 {%0,%1},%2;" : "=f"(v.x), "=f"(v.y) : "l"(a)); return v;
}
__device__ __forceinline__ void fma2(u64& d, u64 a, u64 b) {
    asm("fma.rn.f32x2 %0,%1,%2,%0;" : "+l"(d) : "l"(a), "l"(b));
}
__device__ __forceinline__ u64 add2(u64 a, u64 b) {
    u64 r; asm("add.rn.f32x2 %0,%1,%2;" : "=l"(r) : "l"(a), "l"(b)); return r;
}

// ---------------------------------------------------------------------------
// main: 512 CTAs x 256 thr, occ 4.
//   phase A: inline veff prep for (s, t=2ks..2ks+1, o=mt*4..mt*4+4)
//            (W staged through xs/ws smem — both dead until phase B)
//   spin   : wait for the slice's 16 producers (DRAM now idle -> fast veff)
//   phase B: R4-exact GEMM, prologue included
// ---------------------------------------------------------------------------
__global__ void __launch_bounds__(256, 4) main_kernel(
    const float* __restrict__ x, const float* __restrict__ W) {
    __shared__ __align__(16) float xs[2][32][68];  // [buf][ij][b]; aliased as W-staging A
    __shared__ __align__(16) float ws[2][32][64];  // [buf][ij][o]; aliased as W-staging B
    __shared__ __align__(16) float buf1[256];
    __shared__ __align__(16) float buf2[256];
    __shared__ __align__(16) float CtL[64];   // our 2 t-rows: [t01][f]
    __shared__ __align__(16) float CsL[64];   // [i][p]
    __shared__ __align__(16) float CstL[64];  // [q][j]

    const int tid = threadIdx.x;
    const int bx = blockIdx.x;
    const int ks = bx & 15;
    const int mt = (bx >> 4) & 15;
    const int s = bx >> 8;
    const int slice = s * 16 + ks;

    // ======================= phase A: inline veff prep =======================
    {
        // tables (<=1 cospif per thread)
        if (tid < 64) {
            int t01 = tid >> 5, f = tid & 31;
            CtL[tid] = 2.0f * cospif((float)((2 * (ks * 2 + t01) + 1) * f) / 64.0f);
        } else if (tid < 128) {
            int e = tid - 64;
            CsL[e] = 2.0f * cospif((float)((2 * (e >> 3) + 1) * (e & 7)) / 16.0f);
        } else if (tid < 192) {
            int e = tid - 128;  // e = q*8 + j
            CstL[e] = 2.0f * cospif((float)((2 * (e & 7) + 1) * (e >> 3)) / 16.0f);
        }

        // load our 4 o's of W[s] (32 KB): group A = o {0,1}, B = o {2,3}
        const float4* wp = (const float4*)(W + ((size_t)(s * 64 + mt * 4) << 11));
        float4 ra0 = wp[tid], ra1 = wp[tid + 256], ra2 = wp[tid + 512], ra3 = wp[tid + 768];
        float4 rb0 = wp[tid + 1024], rb1 = wp[tid + 1280],
               rb2 = wp[tid + 1536], rb3 = wp[tid + 1792];
        float* WSa = &xs[0][0][0];  // 4096-float staging (xs is dead until GEMM)
        float* WSb = &ws[0][0][0];  // 4096-float staging
        ((float4*)WSa)[tid] = ra0; ((float4*)WSa)[tid + 256] = ra1;
        ((float4*)WSa)[tid + 512] = ra2; ((float4*)WSa)[tid + 768] = ra3;
        ((float4*)WSb)[tid] = rb0; ((float4*)WSb)[tid + 256] = rb1;
        ((float4*)WSb)[tid + 512] = rb2; ((float4*)WSb)[tid + 768] = rb3;
        __syncthreads();

        const int o2 = tid >> 7;          // which o of the pair
        const int t01 = (tid >> 6) & 1;   // which t
        const int pq = tid & 63;
        const int grp = tid & 192;        // o2*128 + t01*64
        const int i3 = (tid >> 3) & 7;    // i (stage2) / i (stage3)
        const int j3 = tid & 7;           // q (stage2) / j (stage3)

#pragma unroll
        for (int og = 0; og < 2; ++og) {
            const float* WS = og ? WSb : WSa;
            // stage 1: f -> t
            float a = 0.0f;
#pragma unroll
            for (int f = 0; f < 32; ++f)
                a = fmaf(CtL[t01 * 32 + f], WS[o2 * 2048 + f * 64 + pq], a);
            buf1[tid] = a;
            __syncthreads();
            // stage 2: p -> i
            float b = 0.0f;
#pragma unroll
            for (int p = 0; p < 8; ++p)
                b = fmaf(CsL[i3 * 8 + p], buf1[grp + p * 8 + j3], b);
            buf2[tid] = b;
            __syncthreads();
            // stage 3: q -> j, scale, store
            float c = 0.0f;
#pragma unroll
            for (int q = 0; q < 8; ++q)
                c = fmaf(CstL[q * 8 + j3], buf2[grp + i3 * 8 + q], c);
            int o = mt * 4 + og * 2 + o2;
            int row = ((s * 32 + ks * 2 + t01) << 6) + i3 * 8 + j3;
            g_veff[(size_t)row * 64 + o] = 0.125f * c;
            __syncthreads();
        }
        __threadfence();
        __syncthreads();
        if (tid == 0) atomicAdd(&g_flag[slice], 1);
    }

    // =================== spin: wait for the slice's producers ===============
    // (x burst intentionally NOT issued yet — keeps DRAM clear for the
    //  W->veff critical path of the slowest peers)
    if (tid == 0) {
        int v;
        do {
            asm volatile("ld.global.acquire.gpu.b32 %0, [%1];"
                         : "=r"(v) : "l"(g_flag + slice) : "memory");
            if (v < 16) __nanosleep(32);
        } while (v < 16);
    }
    __syncthreads();

    // ======================= phase B: R4-exact GEMM =======================
    const int ijp = tid & 15, bb = tid >> 4;  // load map (coalesced 128B rows)
    const int tx = tid & 15, ty = tid >> 4;   // compute map

    const float* xb = x + (size_t)(mt * 64 + bb * 4) * 32768 + (size_t)s * 16384 + 2 * ijp;

    u64 acc[2][4] = {};
    u64 xr[8];
    float4 wr0, wr1;

#define PH_T(ph) (ks * 2 + ((ph) >> 1))
#define PH_OFF(ph) ((size_t)(PH_T(ph)) * 64 + ((ph) & 1) * 32)

#define LDG_U(ph, u)                                                          \
    do {                                                                      \
        const u64* p = (const u64*)(xb + (size_t)(u) * 32768 + PH_OFF(ph));   \
        _Pragma("unroll") for (int c = 0; c < 8; ++c) xr[c] = __ldcs(p + c * 1024); \
    } while (0)

#define STS_U(buf, u)                                                         \
    do {                                                                      \
        u64 s0 = add2(add2(xr[0], xr[1]), add2(xr[2], xr[3]));                \
        u64 s1 = add2(add2(xr[4], xr[5]), add2(xr[6], xr[7]));                \
        float2 v = up2(add2(s0, s1));                                         \
        xs[buf][2 * ijp][bb * 4 + (u)] = v.x;                                 \
        xs[buf][2 * ijp + 1][bb * 4 + (u)] = v.y;                             \
    } while (0)

#define LDG_W(ph)                                                             \
    do {                                                                      \
        const float4* wp2 = (const float4*)(g_veff +                         \
            (((size_t)s * 32 + PH_T(ph)) * 64 + ((ph) & 1) * 32) * 64);       \
        wr0 = wp2[tid]; wr1 = wp2[tid + 256];                                 \
    } while (0)

#define STS_W(buf)                                                            \
    do {                                                                      \
        float4* wd = (float4*)&ws[buf][0][0];                                 \
        wd[tid] = wr0; wd[tid + 256] = wr1;                                   \
    } while (0)

#define COMP8(buf, k0)                                                        \
    do {                                                                      \
        _Pragma("unroll") for (int k = (k0); k < (k0) + 8; ++k) {             \
            ulonglong2 xp = *(const ulonglong2*)&xs[buf][k][4 * ty];          \
            float4 wv = *(const float4*)&ws[buf][k][4 * tx];                  \
            u64 w0 = pk2(wv.x, wv.x), w1 = pk2(wv.y, wv.y);                   \
            u64 w2 = pk2(wv.z, wv.z), w3 = pk2(wv.w, wv.w);                   \
            fma2(acc[0][0], xp.x, w0); fma2(acc[1][0], xp.y, w0);             \
            fma2(acc[0][1], xp.x, w1); fma2(acc[1][1], xp.y, w1);             \
            fma2(acc[0][2], xp.x, w2); fma2(acc[1][2], xp.y, w2);             \
            fma2(acc[0][3], xp.x, w3); fma2(acc[1][3], xp.y, w3);             \
        }                                                                     \
    } while (0)

    // R4-exact prologue: fill buffer 0 with phase 0
    LDG_W(0);
    LDG_U(0, 0); STS_U(0, 0);
    LDG_U(0, 1); STS_U(0, 1);
    LDG_U(0, 2); STS_U(0, 2);
    LDG_U(0, 3); STS_U(0, 3);
    STS_W(0);
    __syncthreads();

#pragma unroll
    for (int ph = 0; ph < 4; ++ph) {
        const int buf = ph & 1, nb = buf ^ 1;
        if (ph < 3) {
            LDG_W(ph + 1);
            LDG_U(ph + 1, 0); COMP8(buf, 0);  STS_U(nb, 0);
            LDG_U(ph + 1, 1); COMP8(buf, 8);  STS_U(nb, 1);
            LDG_U(ph + 1, 2); COMP8(buf, 16); STS_U(nb, 2);
            LDG_U(ph + 1, 3); COMP8(buf, 24); STS_U(nb, 3);
            STS_W(nb);
        } else {
            COMP8(buf, 0); COMP8(buf, 8); COMP8(buf, 16); COMP8(buf, 24);
        }
        __syncthreads();
    }

    // write partials: g_part[ks][b][s*64+o]
    const int b0 = mt * 64 + 4 * ty;
    const int obase = s * 64 + 4 * tx;
#pragma unroll
    for (int p = 0; p < 2; ++p) {
        float2 c0 = up2(acc[p][0]), c1 = up2(acc[p][1]);
        float2 c2 = up2(acc[p][2]), c3 = up2(acc[p][3]);
        float4 r0 = make_float4(c0.x, c1.x, c2.x, c3.x);
        float4 r1 = make_float4(c0.y, c1.y, c2.y, c3.y);
        __stcs((float4*)(g_part + ((size_t)ks << 17) + (size_t)(b0 + 2 * p) * 128 + obase), r0);
        __stcs((float4*)(g_part + ((size_t)ks << 17) + (size_t)(b0 + 2 * p + 1) * 128 + obase), r1);
    }
}

// ---------------------------------------------------------------------------
// epilogue: sum KSPLIT partials + bias, LeakyReLU; resets slice flags.
// ---------------------------------------------------------------------------
__global__ void __launch_bounds__(256) epi_kernel(const float* __restrict__ bias,
                                                  float* __restrict__ out) {
    if (blockIdx.x == 0 && threadIdx.x < 32) g_flag[threadIdx.x] = 0;  // next replay

    const int i4 = (blockIdx.x * 256 + threadIdx.x) * 4;
    float4 bv = *(const float4*)(bias + (i4 & 127));
    u64 a0 = pk2(bv.x, bv.y), a1 = pk2(bv.z, bv.w);
#pragma unroll
    for (int k = 0; k < KSPLIT; ++k) {
        const ulonglong2* pp = (const ulonglong2*)(g_part + ((size_t)k << 17) + i4);
        ulonglong2 p;
        p.x = __ldcs(&pp->x);
        p.y = __ldcs(&pp->y);
        a0 = add2(a0, p.x);
        a1 = add2(a1, p.y);
    }
    float2 f0 = up2(a0), f1 = up2(a1);
    float4 r;
    r.x = (f0.x >= 0.0f) ? f0.x : 0.02f * f0.x;
    r.y = (f0.y >= 0.0f) ? f0.y : 0.02f * f0.y;
    r.z = (f1.x >= 0.0f) ? f1.x : 0.02f * f1.x;
    r.w = (f1.y >= 0.0f) ? f1.y : 0.02f * f1.y;
    *(float4*)(out + i4) = r;
}

// ---------------------------------------------------------------------------
extern "C" void kernel_launch(void* const* d_in, const int* in_sizes, int n_in,
                              void* d_out, int out_size) {
    const float* x = nullptr;
    const float* W = nullptr;
    const float* bias = nullptr;
    for (int i = 0; i < n_in; ++i) {
        if (in_sizes[i] == 1024 * 512 * 64) x = (const float*)d_in[i];
        else if (in_sizes[i] == NSW * NF * 32 * 64) W = (const float*)d_in[i];
        else if (in_sizes[i] == NSW * NF) bias = (const float*)d_in[i];
    }
    if (!x) x = (const float*)d_in[0];
    if (!W) W = (const float*)d_in[1];
    if (!bias) bias = (const float*)d_in[2];

    main_kernel<<<NSW * MTILES * KSPLIT, 256>>>(x, W);
    epi_kernel<<<(1024 * NSW * NF) / (256 * 4), 256>>>(bias, (float*)d_out);
}

// round 16
// speedup vs baseline: 1.0452x; 1.0452x over previous
#include <cuda_runtime.h>
#include <cstddef>
#include <cstdint>

// DCTFeatureModel — collapsed linear model:
// feat[b,s,o] = sum_{t,ij} xc[b,s,t,ij] * Veff[s,o,t,ij] + bias[s,o]
//   xc[b,s,t,ij]    = sum_c x[b, s*256 + c*32 + t, ij]
//   Veff[s,o,t,i,j] = (1/8) sum_{f,p,q} Ct[f,t] Cs[p,i] Cs[q,j] W[s,o,f,p,q]
// out[b, s*64+o] = leaky_relu(feat)
//
// FINAL (= R13, best measured 38.98us): prep fused into main. Each CTA
// (s,ks,mt) computes its own veff sub-slice (2 t's x 4 o's), publishes via
// per-(s,ks) flag (16 arrivals), issues its phase-0 x tile BEFORE spinning
// (the spin absorbs the first DRAM round-trip), then runs the R4-exact GEMM.
// epi separate + resets flags for the next graph replay.

#define NSW 2
#define NF 64
#define KSPLIT 16
#define MTILES 16

__device__ __align__(16) float g_veff[NSW * 32 * 64 * 64];        // [s][t][ij][o], 1 MB
__device__ __align__(16) float g_part[KSPLIT * 1024 * NSW * NF];  // 8 MB
__device__ int g_flag[32];  // per-(s,ks) slice arrival counters; epi resets

typedef unsigned long long u64;

__device__ __forceinline__ u64 pk2(float a, float b) {
    u64 r; asm("mov.b64 %0,{%1,%2};" : "=l"(r) : "f"(a), "f"(b)); return r;
}
__device__ __forceinline__ float2 up2(u64 a) {
    float2 v; asm("mov.b64 {%0,%1},%2;" : "=f"(v.x), "=f"(v.y) : "l"(a)); return v;
}
__device__ __forceinline__ void fma2(u64& d, u64 a, u64 b) {
    asm("fma.rn.f32x2 %0,%1,%2,%0;" : "+l"(d) : "l"(a), "l"(b));
}
__device__ __forceinline__ u64 add2(u64 a, u64 b) {
    u64 r; asm("add.rn.f32x2 %0,%1,%2;" : "=l"(r) : "l"(a), "l"(b)); return r;
}

// ---------------------------------------------------------------------------
// main: 512 CTAs x 256 thr, occ 4.
//   phase A: inline veff prep for (s, t=2ks..2ks+1, o=mt*4..mt*4+4)
//   phase B: R4-exact GEMM (phase-0 x prefetched before the slice spin)
// ---------------------------------------------------------------------------
__global__ void __launch_bounds__(256, 4) main_kernel(
    const float* __restrict__ x, const float* __restrict__ W) {
    __shared__ __align__(16) float xs[2][32][68];  // [buf][ij][b]; aliased as W-staging A
    __shared__ __align__(16) float ws[2][32][64];  // [buf][ij][o]; aliased as W-staging B
    __shared__ __align__(16) float buf1[256];
    __shared__ __align__(16) float buf2[256];
    __shared__ __align__(16) float CtL[64];   // our 2 t-rows: [t01][f]
    __shared__ __align__(16) float CsL[64];   // [i][p]
    __shared__ __align__(16) float CstL[64];  // [q][j]

    const int tid = threadIdx.x;
    const int bx = blockIdx.x;
    const int ks = bx & 15;
    const int mt = (bx >> 4) & 15;
    const int s = bx >> 8;
    const int slice = s * 16 + ks;

    // ======================= phase A: inline veff prep =======================
    {
        // tables (<=1 cospif per thread)
        if (tid < 64) {
            int t01 = tid >> 5, f = tid & 31;
            CtL[tid] = 2.0f * cospif((float)((2 * (ks * 2 + t01) + 1) * f) / 64.0f);
        } else if (tid < 128) {
            int e = tid - 64;
            CsL[e] = 2.0f * cospif((float)((2 * (e >> 3) + 1) * (e & 7)) / 16.0f);
        } else if (tid < 192) {
            int e = tid - 128;  // e = q*8 + j
            CstL[e] = 2.0f * cospif((float)((2 * (e & 7) + 1) * (e >> 3)) / 16.0f);
        }

        // load our 4 o's of W[s] (32 KB): group A = o {0,1}, B = o {2,3}
        const float4* wp = (const float4*)(W + ((size_t)(s * 64 + mt * 4) << 11));
        float4 ra0 = wp[tid], ra1 = wp[tid + 256], ra2 = wp[tid + 512], ra3 = wp[tid + 768];
        float4 rb0 = wp[tid + 1024], rb1 = wp[tid + 1280],
               rb2 = wp[tid + 1536], rb3 = wp[tid + 1792];
        float* WSa = &xs[0][0][0];  // 4096-float staging (xs is dead until GEMM)
        float* WSb = &ws[0][0][0];  // 4096-float staging
        ((float4*)WSa)[tid] = ra0; ((float4*)WSa)[tid + 256] = ra1;
        ((float4*)WSa)[tid + 512] = ra2; ((float4*)WSa)[tid + 768] = ra3;
        ((float4*)WSb)[tid] = rb0; ((float4*)WSb)[tid + 256] = rb1;
        ((float4*)WSb)[tid + 512] = rb2; ((float4*)WSb)[tid + 768] = rb3;
        __syncthreads();

        const int o2 = tid >> 7;          // which o of the pair
        const int t01 = (tid >> 6) & 1;   // which t
        const int pq = tid & 63;
        const int grp = tid & 192;        // o2*128 + t01*64
        const int i3 = (tid >> 3) & 7;    // i (stage2) / i (stage3)
        const int j3 = tid & 7;           // q (stage2) / j (stage3)

#pragma unroll
        for (int og = 0; og < 2; ++og) {
            const float* WS = og ? WSb : WSa;
            // stage 1: f -> t
            float a = 0.0f;
#pragma unroll
            for (int f = 0; f < 32; ++f)
                a = fmaf(CtL[t01 * 32 + f], WS[o2 * 2048 + f * 64 + pq], a);
            buf1[tid] = a;
            __syncthreads();
            // stage 2: p -> i
            float b = 0.0f;
#pragma unroll
            for (int p = 0; p < 8; ++p)
                b = fmaf(CsL[i3 * 8 + p], buf1[grp + p * 8 + j3], b);
            buf2[tid] = b;
            __syncthreads();
            // stage 3: q -> j, scale, store
            float c = 0.0f;
#pragma unroll
            for (int q = 0; q < 8; ++q)
                c = fmaf(CstL[q * 8 + j3], buf2[grp + i3 * 8 + q], c);
            int o = mt * 4 + og * 2 + o2;
            int row = ((s * 32 + ks * 2 + t01) << 6) + i3 * 8 + j3;
            g_veff[(size_t)row * 64 + o] = 0.125f * c;
            __syncthreads();
        }
        __threadfence();
        __syncthreads();
        if (tid == 0) atomicAdd(&g_flag[slice], 1);
    }

    // ======================= phase B: R4-exact GEMM =======================
    const int ijp = tid & 15, bb = tid >> 4;  // load map (coalesced 128B rows)
    const int tx = tid & 15, ty = tid >> 4;   // compute map

    const float* xb = x + (size_t)(mt * 64 + bb * 4) * 32768 + (size_t)s * 16384 + 2 * ijp;

    u64 acc[2][4] = {};
    u64 xr[8];
    float4 wr0, wr1;

#define PH_T(ph) (ks * 2 + ((ph) >> 1))
#define PH_OFF(ph) ((size_t)(PH_T(ph)) * 64 + ((ph) & 1) * 32)

#define LDG_U(ph, u)                                                          \
    do {                                                                      \
        const u64* p = (const u64*)(xb + (size_t)(u) * 32768 + PH_OFF(ph));   \
        _Pragma("unroll") for (int c = 0; c < 8; ++c) xr[c] = __ldcs(p + c * 1024); \
    } while (0)

#define STS_U(buf, u)                                                         \
    do {                                                                      \
        u64 s0 = add2(add2(xr[0], xr[1]), add2(xr[2], xr[3]));                \
        u64 s1 = add2(add2(xr[4], xr[5]), add2(xr[6], xr[7]));                \
        float2 v = up2(add2(s0, s1));                                         \
        xs[buf][2 * ijp][bb * 4 + (u)] = v.x;                                 \
        xs[buf][2 * ijp + 1][bb * 4 + (u)] = v.y;                             \
    } while (0)

#define LDG_W(ph)                                                             \
    do {                                                                      \
        const float4* wp2 = (const float4*)(g_veff +                         \
            (((size_t)s * 32 + PH_T(ph)) * 64 + ((ph) & 1) * 32) * 64);       \
        wr0 = wp2[tid]; wr1 = wp2[tid + 256];                                 \
    } while (0)

#define STS_W(buf)                                                            \
    do {                                                                      \
        float4* wd = (float4*)&ws[buf][0][0];                                 \
        wd[tid] = wr0; wd[tid + 256] = wr1;                                   \
    } while (0)

#define COMP8(buf, k0)                                                        \
    do {                                                                      \
        _Pragma("unroll") for (int k = (k0); k < (k0) + 8; ++k) {             \
            ulonglong2 xp = *(const ulonglong2*)&xs[buf][k][4 * ty];          \
            float4 wv = *(const float4*)&ws[buf][k][4 * tx];                  \
            u64 w0 = pk2(wv.x, wv.x), w1 = pk2(wv.y, wv.y);                   \
            u64 w2 = pk2(wv.z, wv.z), w3 = pk2(wv.w, wv.w);                   \
            fma2(acc[0][0], xp.x, w0); fma2(acc[1][0], xp.y, w0);             \
            fma2(acc[0][1], xp.x, w1); fma2(acc[1][1], xp.y, w1);             \
            fma2(acc[0][2], xp.x, w2); fma2(acc[1][2], xp.y, w2);             \
            fma2(acc[0][3], xp.x, w3); fma2(acc[1][3], xp.y, w3);             \
        }                                                                     \
    } while (0)

    // phase-0 x prefetch + c-reduce into xs[0] BEFORE the slice spin
    LDG_U(0, 0); STS_U(0, 0);
    LDG_U(0, 1); STS_U(0, 1);
    LDG_U(0, 2); STS_U(0, 2);
    LDG_U(0, 3); STS_U(0, 3);

    // wait for our slice's 16 producers
    if (tid == 0) {
        int v;
        do {
            asm volatile("ld.global.acquire.gpu.b32 %0, [%1];"
                         : "=r"(v) : "l"(g_flag + slice) : "memory");
            if (v < 16) __nanosleep(32);
        } while (v < 16);
    }
    __syncthreads();

    LDG_W(0);
    STS_W(0);
    __syncthreads();

#pragma unroll
    for (int ph = 0; ph < 4; ++ph) {
        const int buf = ph & 1, nb = buf ^ 1;
        if (ph < 3) {
            LDG_W(ph + 1);
            LDG_U(ph + 1, 0); COMP8(buf, 0);  STS_U(nb, 0);
            LDG_U(ph + 1, 1); COMP8(buf, 8);  STS_U(nb, 1);
            LDG_U(ph + 1, 2); COMP8(buf, 16); STS_U(nb, 2);
            LDG_U(ph + 1, 3); COMP8(buf, 24); STS_U(nb, 3);
            STS_W(nb);
        } else {
            COMP8(buf, 0); COMP8(buf, 8); COMP8(buf, 16); COMP8(buf, 24);
        }
        __syncthreads();
    }

    // write partials: g_part[ks][b][s*64+o]
    const int b0 = mt * 64 + 4 * ty;
    const int obase = s * 64 + 4 * tx;
#pragma unroll
    for (int p = 0; p < 2; ++p) {
        float2 c0 = up2(acc[p][0]), c1 = up2(acc[p][1]);
        float2 c2 = up2(acc[p][2]), c3 = up2(acc[p][3]);
        float4 r0 = make_float4(c0.x, c1.x, c2.x, c3.x);
        float4 r1 = make_float4(c0.y, c1.y, c2.y, c3.y);
        __stcs((float4*)(g_part + ((size_t)ks << 17) + (size_t)(b0 + 2 * p) * 128 + obase), r0);
        __stcs((float4*)(g_part + ((size_t)ks << 17) + (size_t)(b0 + 2 * p + 1) * 128 + obase), r1);
    }
}

// ---------------------------------------------------------------------------
// epilogue: sum KSPLIT partials + bias, LeakyReLU; resets slice flags.
// ---------------------------------------------------------------------------
__global__ void __launch_bounds__(256) epi_kernel(const float* __restrict__ bias,
                                                  float* __restrict__ out) {
    if (blockIdx.x == 0 && threadIdx.x < 32) g_flag[threadIdx.x] = 0;  // next replay

    const int i4 = (blockIdx.x * 256 + threadIdx.x) * 4;
    float4 bv = *(const float4*)(bias + (i4 & 127));
    u64 a0 = pk2(bv.x, bv.y), a1 = pk2(bv.z, bv.w);
#pragma unroll
    for (int k = 0; k < KSPLIT; ++k) {
        const ulonglong2* pp = (const ulonglong2*)(g_part + ((size_t)k << 17) + i4);
        ulonglong2 p;
        p.x = __ldcs(&pp->x);
        p.y = __ldcs(&pp->y);
        a0 = add2(a0, p.x);
        a1 = add2(a1, p.y);
    }
    float2 f0 = up2(a0), f1 = up2(a1);
    float4 r;
    r.x = (f0.x >= 0.0f) ? f0.x : 0.02f * f0.x;
    r.y = (f0.y >= 0.0f) ? f0.y : 0.02f * f0.y;
    r.z = (f1.x >= 0.0f) ? f1.x : 0.02f * f1.x;
    r.w = (f1.y >= 0.0f) ? f1.y : 0.02f * f1.y;
    *(float4*)(out + i4) = r;
}

// ---------------------------------------------------------------------------
extern "C" void kernel_launch(void* const* d_in, const int* in_sizes, int n_in,
                              void* d_out, int out_size) {
    const float* x = nullptr;
    const float* W = nullptr;
    const float* bias = nullptr;
    for (int i = 0; i < n_in; ++i) {
        if (in_sizes[i] == 1024 * 512 * 64) x = (const float*)d_in[i];
        else if (in_sizes[i] == NSW * NF * 32 * 64) W = (const float*)d_in[i];
        else if (in_sizes[i] == NSW * NF) bias = (const float*)d_in[i];
    }
    if (!x) x = (const float*)d_in[0];
    if (!W) W = (const float*)d_in[1];
    if (!bias) bias = (const float*)d_in[2];

    main_kernel<<<NSW * MTILES * KSPLIT, 256>>>(x, W);
    epi_kernel<<<(1024 * NSW * NF) / (256 * 4), 256>>>(bias, (float*)d_out);
}

// round 17
// speedup vs baseline: 1.0519x; 1.0065x over previous
#include <cuda_runtime.h>
#include <cstddef>
#include <cstdint>

// DCTFeatureModel — collapsed linear model:
// feat[b,s,o] = sum_{t,ij} xc[b,s,t,ij] * Veff[s,o,t,ij] + bias[s,o]
//   xc[b,s,t,ij]    = sum_c x[b, s*256 + c*32 + t, ij]
//   Veff[s,o,t,i,j] = (1/8) sum_{f,p,q} Ct[f,t] Cs[p,i] Cs[q,j] W[s,o,f,p,q]
// out[b, s*64+o] = leaky_relu(feat)
//
// R17 = R13 (best measured, 38.98us) with ONE isolated delta: phase A
// processes both o-groups per stage pass (ILP 2, 3 fewer barriers).
// W smem staging, x-prefetch-before-spin ordering, GEMM loop, partial
// stores and epi are byte-identical to R13.

#define NSW 2
#define NF 64
#define KSPLIT 16
#define MTILES 16

__device__ __align__(16) float g_veff[NSW * 32 * 64 * 64];        // [s][t][ij][o], 1 MB
__device__ __align__(16) float g_part[KSPLIT * 1024 * NSW * NF];  // 8 MB
__device__ int g_flag[32];  // per-(s,ks) slice arrival counters; epi resets

typedef unsigned long long u64;

__device__ __forceinline__ u64 pk2(float a, float b) {
    u64 r; asm("mov.b64 %0,{%1,%2};" : "=l"(r) : "f"(a), "f"(b)); return r;
}
__device__ __forceinline__ float2 up2(u64 a) {
    float2 v; asm("mov.b64 {%0,%1},%2;" : "=f"(v.x), "=f"(v.y) : "l"(a)); return v;
}
__device__ __forceinline__ void fma2(u64& d, u64 a, u64 b) {
    asm("fma.rn.f32x2 %0,%1,%2,%0;" : "+l"(d) : "l"(a), "l"(b));
}
__device__ __forceinline__ u64 add2(u64 a, u64 b) {
    u64 r; asm("add.rn.f32x2 %0,%1,%2;" : "=l"(r) : "l"(a), "l"(b)); return r;
}

// ---------------------------------------------------------------------------
// main: 512 CTAs x 256 thr, occ 4.
//   phase A: inline veff prep for (s, t=2ks..2ks+1, o=mt*4..mt*4+4), ILP-2
//   phase B: R4-exact GEMM (phase-0 x prefetched before the slice spin)
// ---------------------------------------------------------------------------
__global__ void __launch_bounds__(256, 4) main_kernel(
    const float* __restrict__ x, const float* __restrict__ W) {
    __shared__ __align__(16) float xs[2][32][68];  // [buf][ij][b]; aliased as W-staging A
    __shared__ __align__(16) float ws[2][32][64];  // [buf][ij][o]; aliased as W-staging B
    __shared__ __align__(16) float buf1[512];      // [og][o2][t01][pq]
    __shared__ __align__(16) float buf2[512];
    __shared__ __align__(16) float CtL[64];   // our 2 t-rows: [t01][f]
    __shared__ __align__(16) float CsL[64];   // [i][p]
    __shared__ __align__(16) float CstL[64];  // [q][j]

    const int tid = threadIdx.x;
    const int bx = blockIdx.x;
    const int ks = bx & 15;
    const int mt = (bx >> 4) & 15;
    const int s = bx >> 8;
    const int slice = s * 16 + ks;

    // ======================= phase A: inline veff prep =======================
    {
        // tables (<=1 cospif per thread)
        if (tid < 64) {
            int t01 = tid >> 5, f = tid & 31;
            CtL[tid] = 2.0f * cospif((float)((2 * (ks * 2 + t01) + 1) * f) / 64.0f);
        } else if (tid < 128) {
            int e = tid - 64;
            CsL[e] = 2.0f * cospif((float)((2 * (e >> 3) + 1) * (e & 7)) / 16.0f);
        } else if (tid < 192) {
            int e = tid - 128;  // e = q*8 + j
            CstL[e] = 2.0f * cospif((float)((2 * (e & 7) + 1) * (e >> 3)) / 16.0f);
        }

        // load our 4 o's of W[s] (32 KB): group A = o {0,1}, B = o {2,3}
        const float4* wp = (const float4*)(W + ((size_t)(s * 64 + mt * 4) << 11));
        float4 ra0 = wp[tid], ra1 = wp[tid + 256], ra2 = wp[tid + 512], ra3 = wp[tid + 768];
        float4 rb0 = wp[tid + 1024], rb1 = wp[tid + 1280],
               rb2 = wp[tid + 1536], rb3 = wp[tid + 1792];
        float* WSa = &xs[0][0][0];  // 4096-float staging (xs is dead until GEMM)
        float* WSb = &ws[0][0][0];  // 4096-float staging
        ((float4*)WSa)[tid] = ra0; ((float4*)WSa)[tid + 256] = ra1;
        ((float4*)WSa)[tid + 512] = ra2; ((float4*)WSa)[tid + 768] = ra3;
        ((float4*)WSb)[tid] = rb0; ((float4*)WSb)[tid + 256] = rb1;
        ((float4*)WSb)[tid + 512] = rb2; ((float4*)WSb)[tid + 768] = rb3;
        __syncthreads();

        const int o2 = tid >> 7;          // which o of the pair
        const int t01 = (tid >> 6) & 1;   // which t
        const int pq = tid & 63;
        const int grp = tid & 192;        // o2*128 + t01*64
        const int i3 = (tid >> 3) & 7;    // i (stage2) / i (stage3)
        const int j3 = tid & 7;           // q (stage2) / j (stage3)

        // stage 1: f -> t (both og, ILP 2)
        {
            float a0 = 0.0f, a1 = 0.0f;
#pragma unroll
            for (int f = 0; f < 32; ++f) {
                float ct = CtL[t01 * 32 + f];
                a0 = fmaf(ct, WSa[o2 * 2048 + f * 64 + pq], a0);
                a1 = fmaf(ct, WSb[o2 * 2048 + f * 64 + pq], a1);
            }
            buf1[tid] = a0;
            buf1[tid + 256] = a1;
        }
        __syncthreads();

        // stage 2: p -> i (both og)
        {
            float b0 = 0.0f, b1 = 0.0f;
#pragma unroll
            for (int p = 0; p < 8; ++p) {
                float cs = CsL[i3 * 8 + p];
                b0 = fmaf(cs, buf1[grp + p * 8 + j3], b0);
                b1 = fmaf(cs, buf1[256 + grp + p * 8 + j3], b1);
            }
            buf2[tid] = b0;
            buf2[tid + 256] = b1;
        }
        __syncthreads();

        // stage 3: q -> j, scale, scatter (both og)
        {
            float c0 = 0.0f, c1 = 0.0f;
#pragma unroll
            for (int q = 0; q < 8; ++q) {
                float cq = CstL[q * 8 + j3];
                c0 = fmaf(cq, buf2[grp + i3 * 8 + q], c0);
                c1 = fmaf(cq, buf2[256 + grp + i3 * 8 + q], c1);
            }
            int row = ((s * 32 + ks * 2 + t01) << 6) + i3 * 8 + j3;
            int o = mt * 4 + o2;          // og=0 -> o, og=1 -> o+2
            g_veff[(size_t)row * 64 + o] = 0.125f * c0;
            g_veff[(size_t)row * 64 + o + 2] = 0.125f * c1;
        }
        __threadfence();
        __syncthreads();
        if (tid == 0) atomicAdd(&g_flag[slice], 1);
    }

    // ======================= phase B: R4-exact GEMM =======================
    const int ijp = tid & 15, bb = tid >> 4;  // load map (coalesced 128B rows)
    const int tx = tid & 15, ty = tid >> 4;   // compute map

    const float* xb = x + (size_t)(mt * 64 + bb * 4) * 32768 + (size_t)s * 16384 + 2 * ijp;

    u64 acc[2][4] = {};
    u64 xr[8];
    float4 wr0, wr1;

#define PH_T(ph) (ks * 2 + ((ph) >> 1))
#define PH_OFF(ph) ((size_t)(PH_T(ph)) * 64 + ((ph) & 1) * 32)

#define LDG_U(ph, u)                                                          \
    do {                                                                      \
        const u64* p = (const u64*)(xb + (size_t)(u) * 32768 + PH_OFF(ph));   \
        _Pragma("unroll") for (int c = 0; c < 8; ++c) xr[c] = __ldcs(p + c * 1024); \
    } while (0)

#define STS_U(buf, u)                                                         \
    do {                                                                      \
        u64 s0 = add2(add2(xr[0], xr[1]), add2(xr[2], xr[3]));                \
        u64 s1 = add2(add2(xr[4], xr[5]), add2(xr[6], xr[7]));                \
        float2 v = up2(add2(s0, s1));                                         \
        xs[buf][2 * ijp][bb * 4 + (u)] = v.x;                                 \
        xs[buf][2 * ijp + 1][bb * 4 + (u)] = v.y;                             \
    } while (0)

#define LDG_W(ph)                                                             \
    do {                                                                      \
        const float4* wp2 = (const float4*)(g_veff +                         \
            (((size_t)s * 32 + PH_T(ph)) * 64 + ((ph) & 1) * 32) * 64);       \
        wr0 = wp2[tid]; wr1 = wp2[tid + 256];                                 \
    } while (0)

#define STS_W(buf)                                                            \
    do {                                                                      \
        float4* wd = (float4*)&ws[buf][0][0];                                 \
        wd[tid] = wr0; wd[tid + 256] = wr1;                                   \
    } while (0)

#define COMP8(buf, k0)                                                        \
    do {                                                                      \
        _Pragma("unroll") for (int k = (k0); k < (k0) + 8; ++k) {             \
            ulonglong2 xp = *(const ulonglong2*)&xs[buf][k][4 * ty];          \
            float4 wv = *(const float4*)&ws[buf][k][4 * tx];                  \
            u64 w0 = pk2(wv.x, wv.x), w1 = pk2(wv.y, wv.y);                   \
            u64 w2 = pk2(wv.z, wv.z), w3 = pk2(wv.w, wv.w);                   \
            fma2(acc[0][0], xp.x, w0); fma2(acc[1][0], xp.y, w0);             \
            fma2(acc[0][1], xp.x, w1); fma2(acc[1][1], xp.y, w1);             \
            fma2(acc[0][2], xp.x, w2); fma2(acc[1][2], xp.y, w2);             \
            fma2(acc[0][3], xp.x, w3); fma2(acc[1][3], xp.y, w3);             \
        }                                                                     \
    } while (0)

    // phase-0 x prefetch + c-reduce into xs[0] BEFORE the slice spin
    LDG_U(0, 0); STS_U(0, 0);
    LDG_U(0, 1); STS_U(0, 1);
    LDG_U(0, 2); STS_U(0, 2);
    LDG_U(0, 3); STS_U(0, 3);

    // wait for our slice's 16 producers
    if (tid == 0) {
        int v;
        do {
            asm volatile("ld.global.acquire.gpu.b32 %0, [%1];"
                         : "=r"(v) : "l"(g_flag + slice) : "memory");
            if (v < 16) __nanosleep(32);
        } while (v < 16);
    }
    __syncthreads();

    LDG_W(0);
    STS_W(0);
    __syncthreads();

#pragma unroll
    for (int ph = 0; ph < 4; ++ph) {
        const int buf = ph & 1, nb = buf ^ 1;
        if (ph < 3) {
            LDG_W(ph + 1);
            LDG_U(ph + 1, 0); COMP8(buf, 0);  STS_U(nb, 0);
            LDG_U(ph + 1, 1); COMP8(buf, 8);  STS_U(nb, 1);
            LDG_U(ph + 1, 2); COMP8(buf, 16); STS_U(nb, 2);
            LDG_U(ph + 1, 3); COMP8(buf, 24); STS_U(nb, 3);
            STS_W(nb);
        } else {
            COMP8(buf, 0); COMP8(buf, 8); COMP8(buf, 16); COMP8(buf, 24);
        }
        __syncthreads();
    }

    // write partials: g_part[ks][b][s*64+o]
    const int b0 = mt * 64 + 4 * ty;
    const int obase = s * 64 + 4 * tx;
#pragma unroll
    for (int p = 0; p < 2; ++p) {
        float2 c0 = up2(acc[p][0]), c1 = up2(acc[p][1]);
        float2 c2 = up2(acc[p][2]), c3 = up2(acc[p][3]);
        float4 r0 = make_float4(c0.x, c1.x, c2.x, c3.x);
        float4 r1 = make_float4(c0.y, c1.y, c2.y, c3.y);
        __stcs((float4*)(g_part + ((size_t)ks << 17) + (size_t)(b0 + 2 * p) * 128 + obase), r0);
        __stcs((float4*)(g_part + ((size_t)ks << 17) + (size_t)(b0 + 2 * p + 1) * 128 + obase), r1);
    }
}

// ---------------------------------------------------------------------------
// epilogue: sum KSPLIT partials + bias, LeakyReLU; resets slice flags.
// ---------------------------------------------------------------------------
__global__ void __launch_bounds__(256) epi_kernel(const float* __restrict__ bias,
                                                  float* __restrict__ out) {
    if (blockIdx.x == 0 && threadIdx.x < 32) g_flag[threadIdx.x] = 0;  // next replay

    const int i4 = (blockIdx.x * 256 + threadIdx.x) * 4;
    float4 bv = *(const float4*)(bias + (i4 & 127));
    u64 a0 = pk2(bv.x, bv.y), a1 = pk2(bv.z, bv.w);
#pragma unroll
    for (int k = 0; k < KSPLIT; ++k) {
        const ulonglong2* pp = (const ulonglong2*)(g_part + ((size_t)k << 17) + i4);
        ulonglong2 p;
        p.x = __ldcs(&pp->x);
        p.y = __ldcs(&pp->y);
        a0 = add2(a0, p.x);
        a1 = add2(a1, p.y);
    }
    float2 f0 = up2(a0), f1 = up2(a1);
    float4 r;
    r.x = (f0.x >= 0.0f) ? f0.x : 0.02f * f0.x;
    r.y = (f0.y >= 0.0f) ? f0.y : 0.02f * f0.y;
    r.z = (f1.x >= 0.0f) ? f1.x : 0.02f * f1.x;
    r.w = (f1.y >= 0.0f) ? f1.y : 0.02f * f1.y;
    *(float4*)(out + i4) = r;
}

// ---------------------------------------------------------------------------
extern "C" void kernel_launch(void* const* d_in, const int* in_sizes, int n_in,
                              void* d_out, int out_size) {
    const float* x = nullptr;
    const float* W = nullptr;
    const float* bias = nullptr;
    for (int i = 0; i < n_in; ++i) {
        if (in_sizes[i] == 1024 * 512 * 64) x = (const float*)d_in[i];
        else if (in_sizes[i] == NSW * NF * 32 * 64) W = (const float*)d_in[i];
        else if (in_sizes[i] == NSW * NF) bias = (const float*)d_in[i];
    }
    if (!x) x = (const float*)d_in[0];
    if (!W) W = (const float*)d_in[1];
    if (!bias) bias = (const float*)d_in[2];

    main_kernel<<<NSW * MTILES * KSPLIT, 256>>>(x, W);
    epi_kernel<<<(1024 * NSW * NF) / (256 * 4), 256>>>(bias, (float*)d_out);
}